// round 12
// baseline (speedup 1.0000x reference)
#include <cuda_runtime.h>
#include <cuda_fp16.h>
#include <cstdint>

#define NG   16
#define NPTS 2048
#define DIM  128
#define THRESH 1e-5f
#define LDA  136    // smem row stride in halves

// Scratch (static device globals; no allocations anywhere)
__device__ float  g_Xb[(size_t)NG*NPTS*DIM];          // fp32 Xb
__device__ __half g_Xh[(size_t)NG*NPTS*DIM];          // fp16 Xb (MMA)
__device__ float  g_diag[NG*NPTS];
__device__ float  g_colsum[NG*NPTS];
__device__ __half g_K[(size_t)NG*NPTS*NPTS];          // upper tiles only
__device__ float  g_v[9][NG*NPTS];
__device__ float  g_y[9][NG*NPTS];
__device__ float  g_part[NG*16*5*DIM*2];              // feats partials

// ---------------------------------------------------------------------------
// helpers (baseline PTX only: ldmatrix sm_75+, mma.sync + cp.async sm_80+)
// ---------------------------------------------------------------------------
__device__ __forceinline__ uint32_t smem_u32(const void* p) {
    return (uint32_t)__cvta_generic_to_shared(p);
}
__device__ __forceinline__ void cp16(uint32_t dst, const void* src) {
    asm volatile("cp.async.cg.shared.global [%0], [%1], 16;"
                 :: "r"(dst), "l"(src));
}
__device__ __forceinline__ void cp_commit() {
    asm volatile("cp.async.commit_group;" ::: "memory");
}
__device__ __forceinline__ void cp_wait0() {
    asm volatile("cp.async.wait_group 0;" ::: "memory");
}
__device__ __forceinline__ void cp_wait1() {
    asm volatile("cp.async.wait_group 1;" ::: "memory");
}
__device__ __forceinline__ void ldm_x4(uint32_t* r, uint32_t addr) {
    asm volatile("ldmatrix.sync.aligned.m8n8.x4.shared.b16 {%0,%1,%2,%3}, [%4];"
                 : "=r"(r[0]), "=r"(r[1]), "=r"(r[2]), "=r"(r[3]) : "r"(addr));
}
__device__ __forceinline__ void ldm_x4_trans(uint32_t* r, uint32_t addr) {
    asm volatile("ldmatrix.sync.aligned.m8n8.x4.trans.shared.b16 {%0,%1,%2,%3}, [%4];"
                 : "=r"(r[0]), "=r"(r[1]), "=r"(r[2]), "=r"(r[3]) : "r"(addr));
}
__device__ __forceinline__ void mma16816(float* c, const uint32_t* a,
                                         uint32_t b0, uint32_t b1) {
    asm volatile(
        "mma.sync.aligned.m16n8k16.row.col.f32.f16.f16.f32 "
        "{%0,%1,%2,%3}, {%4,%5,%6,%7}, {%8,%9}, {%0,%1,%2,%3};"
        : "+f"(c[0]), "+f"(c[1]), "+f"(c[2]), "+f"(c[3])
        : "r"(a[0]), "r"(a[1]), "r"(a[2]), "r"(a[3]), "r"(b0), "r"(b1));
}

// ---------------------------------------------------------------------------
// Kernel 1: Xb = pc*alpha (fp32 + fp16), diag, zero colsum + y buffers
// ---------------------------------------------------------------------------
__global__ void prep_kernel(const float* __restrict__ pc,
                            const float* __restrict__ al) {
    int gid = blockIdx.x;
    int g = gid >> 11;
    int n = gid & 2047;
    int b = g >> 2, w = g & 3;
    int c = threadIdx.x;
    float x = pc[((size_t)(b << 11) + n) * DIM + c] * al[w * DIM + c];
    g_Xb[(size_t)gid * DIM + c] = x;
    g_Xh[(size_t)gid * DIM + c] = __float2half_rn(x);
    float s = x * x;
    #pragma unroll
    for (int o = 16; o; o >>= 1) s += __shfl_xor_sync(0xffffffffu, s, o);
    __shared__ float red[4];
    if ((c & 31) == 0) red[c >> 5] = s;
    __syncthreads();
    if (c == 0) {
        g_diag[gid]   = red[0] + red[1] + red[2] + red[3];
        g_colsum[gid] = 0.f;
    }
    if (c >= 1 && c <= 8) g_y[c][gid] = 0.f;
}

// ---------------------------------------------------------------------------
// Kernel 2: HMMA Gram, upper-triangular tile pairs only (136 per graph).
// exp epilogue, fused row/col sums -> colsum. Upper tiles stored only.
// ---------------------------------------------------------------------------
#define GRAM_SMEM (2 * 128 * LDA * 2)

__global__ void __launch_bounds__(256) gram_mma_kernel(const float* __restrict__ sigma) {
    extern __shared__ __half smem[];
    __shared__ float dj_s[128];
    __shared__ float rs_s[128];
    __shared__ float cs_s[128];

    int tid = threadIdx.x, wid = tid >> 5, lane = tid & 31;
    int g = blockIdx.y;

    int idx = blockIdx.x, ti = 0;
    while (idx >= 16 - ti) { idx -= 16 - ti; ti++; }
    int tj = ti + idx;

    int warp_m = wid & 1;
    int warp_n = wid >> 1;

    __half* sA = smem;
    __half* sB = smem + 128 * LDA;
    uint32_t sAu = smem_u32(sA), sBu = smem_u32(sB);

    const __half* XA = g_Xh + ((size_t)g * NPTS + ti * 128) * DIM;
    const __half* XB = g_Xh + ((size_t)g * NPTS + tj * 128) * DIM;
    #pragma unroll
    for (int l = 0; l < 8; l++) {
        int ch  = tid + l * 256;
        int row = ch >> 4;
        int c8  = (ch & 15) << 3;
        uint32_t off = (uint32_t)(row * LDA + c8) << 1;
        cp16(sAu + off, &XA[(size_t)row * DIM + c8]);
        cp16(sBu + off, &XB[(size_t)row * DIM + c8]);
    }
    cp_commit();
    if (tid < 128) {
        dj_s[tid] = g_diag[g * NPTS + tj * 128 + tid];
        rs_s[tid] = 0.f;
        cs_s[tid] = 0.f;
    }
    cp_wait0();
    __syncthreads();

    uint32_t aBase = sAu +
        (((warp_m * 64 + (lane & 15)) * LDA + ((lane >> 4) << 3)) << 1);
    uint32_t bBase = sBu +
        (((warp_n * 32 + (lane & 15)) * LDA + ((lane >> 4) << 3)) << 1);

    float acc[4][4][4];
    #pragma unroll
    for (int mi = 0; mi < 4; mi++)
        #pragma unroll
        for (int ni = 0; ni < 4; ni++)
            #pragma unroll
            for (int e = 0; e < 4; e++) acc[mi][ni][e] = 0.f;

    #pragma unroll
    for (int ks = 0; ks < 8; ks++) {
        uint32_t Af[4][4], Bf[2][4];
        #pragma unroll
        for (int mi = 0; mi < 4; mi++)
            ldm_x4(Af[mi], aBase + ((mi * 16 * LDA + ks * 16) << 1));
        #pragma unroll
        for (int nj = 0; nj < 2; nj++)
            ldm_x4(Bf[nj], bBase + ((nj * 16 * LDA + ks * 16) << 1));
        #pragma unroll
        for (int mi = 0; mi < 4; mi++)
            #pragma unroll
            for (int ni = 0; ni < 4; ni++)
                mma16816(acc[mi][ni], Af[mi],
                         Bf[ni >> 1][ni & 1], Bf[ni >> 1][2 + (ni & 1)]);
    }

    float inv_s = 1.0f / *sigma;
    int r = lane >> 2, q = lane & 3;
    uint32_t h_up[4][4], h_lo[4][4];
    float csA[4] = {0.f, 0.f, 0.f, 0.f};
    float csB[4] = {0.f, 0.f, 0.f, 0.f};

    #pragma unroll
    for (int mi = 0; mi < 4; mi++) {
        int lr0 = warp_m * 64 + mi * 16 + r;
        float di0 = g_diag[g * NPTS + ti * 128 + lr0];
        float di1 = g_diag[g * NPTS + ti * 128 + lr0 + 8];
        float rs0 = 0.f, rs1 = 0.f;
        #pragma unroll
        for (int ni = 0; ni < 4; ni++) {
            int lc = warp_n * 32 + ni * 8 + q * 2;
            float dj0 = dj_s[lc], dj1 = dj_s[lc + 1];
            float* a = acc[mi][ni];
            float k00 = __expf(-(di0 + dj0 - 2.0f * a[0]) * inv_s);
            float k01 = __expf(-(di0 + dj1 - 2.0f * a[1]) * inv_s);
            float k10 = __expf(-(di1 + dj0 - 2.0f * a[2]) * inv_s);
            float k11 = __expf(-(di1 + dj1 - 2.0f * a[3]) * inv_s);
            k00 = (k00 < THRESH) ? 0.f : k00;
            k01 = (k01 < THRESH) ? 0.f : k01;
            k10 = (k10 < THRESH) ? 0.f : k10;
            k11 = (k11 < THRESH) ? 0.f : k11;
            rs0 += k00 + k01;
            rs1 += k10 + k11;
            csA[ni] += k00 + k10;
            csB[ni] += k01 + k11;
            __half2 h0 = __floats2half2_rn(k00, k01);
            __half2 h1 = __floats2half2_rn(k10, k11);
            h_up[mi][ni] = *reinterpret_cast<uint32_t*>(&h0);
            h_lo[mi][ni] = *reinterpret_cast<uint32_t*>(&h1);
        }
        rs0 += __shfl_xor_sync(0xffffffffu, rs0, 1);
        rs0 += __shfl_xor_sync(0xffffffffu, rs0, 2);
        rs1 += __shfl_xor_sync(0xffffffffu, rs1, 1);
        rs1 += __shfl_xor_sync(0xffffffffu, rs1, 2);
        if (q == 0) {
            atomicAdd(&rs_s[lr0], rs0);
            atomicAdd(&rs_s[lr0 + 8], rs1);
        }
    }
    #pragma unroll
    for (int ni = 0; ni < 4; ni++) {
        float a = csA[ni], b = csB[ni];
        #pragma unroll
        for (int o = 4; o <= 16; o <<= 1) {
            a += __shfl_xor_sync(0xffffffffu, a, o);
            b += __shfl_xor_sync(0xffffffffu, b, o);
        }
        if (r == 0) {
            atomicAdd(&cs_s[warp_n * 32 + ni * 8 + 2 * q], a);
            atomicAdd(&cs_s[warp_n * 32 + ni * 8 + 2 * q + 1], b);
        }
    }

    __half* Kg = g_K + (size_t)g * NPTS * NPTS;
    #pragma unroll
    for (int mi = 0; mi < 4; mi++) {
        int lr0 = warp_m * 64 + mi * 16 + r;
        #pragma unroll
        for (int ni = 0; ni < 4; ni++) {
            int lc = warp_n * 32 + ni * 8 + q * 2;
            size_t c0 = (size_t)(ti * 128 + lr0) * NPTS + tj * 128 + lc;
            *(uint32_t*)&Kg[c0]                    = h_up[mi][ni];
            *(uint32_t*)&Kg[c0 + 8 * (size_t)NPTS] = h_lo[mi][ni];
        }
    }

    __syncthreads();
    if (tid < 128) {
        atomicAdd(&g_colsum[g * NPTS + ti * 128 + tid], rs_s[tid]);
        if (ti != tj)
            atomicAdd(&g_colsum[g * NPTS + tj * 128 + tid], cs_s[tid]);
    }
}

// ---------------------------------------------------------------------------
// Kernel 3 (x8): fused normalize + symmetric mat-vec on tensor pipe, with a
// quarter-tile (32 rows) double-buffered cp.async pipeline so each CTA
// streams continuously.
//   row pass (quarter q): 8 warps split (row-half, kc-pair); y[ti] atomics.
//   transpose pass: quarter q supplies k-chunks {2q,2q+1}; d accumulated
//   across quarters in registers; y[tj] atomics at end.
// ---------------------------------------------------------------------------
__global__ void __launch_bounds__(256) step_mma_kernel(int s) {
    __shared__ __half qbuf[2][32 * LDA];     // 2 x 8704 B
    __shared__ __half vti_h[128];
    __shared__ __half vtj_h[128];

    int tid = threadIdx.x, wid = tid >> 5, lane = tid & 31;
    int g = blockIdx.y;
    int idx = blockIdx.x, ti = 0;
    while (idx >= 16 - ti) { idx -= 16 - ti; ti++; }
    int tj = ti + idx;
    bool offdiag = (ti != tj);
    int base_ti = g * NPTS + ti * 128;
    int base_tj = g * NPTS + tj * 128;

    const __half* Kt = g_K + ((size_t)g * NPTS + ti * 128) * NPTS + tj * 128;
    uint32_t qb[2] = {smem_u32(qbuf[0]), smem_u32(qbuf[1])};

    // per-thread copy slots: rows rl0, rl0+16 of the quarter, 16B chunk c16
    int rl0 = tid >> 4;          // 0..15
    int c16 = tid & 15;          // 16B chunk (8 halves)

    // issue quarter 0
    {
        const __half* src = Kt;  // rows 0..31
        cp16(qb[0] + ((uint32_t)(rl0 * LDA + c16 * 8) << 1),
             &src[(size_t)rl0 * NPTS + c16 * 8]);
        cp16(qb[0] + ((uint32_t)((rl0 + 16) * LDA + c16 * 8) << 1),
             &src[(size_t)(rl0 + 16) * NPTS + c16 * 8]);
    }
    cp_commit();

    // normalize phase overlaps the first copy
    if (s == 0) {
        __half h0 = __float2half_rn(1.0f / (float)NPTS);   // exact in fp16
        if (tid < 128) vti_h[tid] = h0;
        else           vtj_h[tid - 128] = h0;
    } else {
        if (tid < 128) {
            int ix = base_ti + tid;
            float vprev = (s == 1) ? (1.0f / (float)NPTS) : g_v[s - 1][ix];
            float nv = 0.5f * g_y[s][ix] / g_colsum[ix] + 0.5f * vprev;
            g_v[s][ix] = nv;                 // redundant identical writes
            vti_h[tid] = __float2half_rn(nv);
        } else {
            int ix = base_tj + (tid - 128);
            float vprev = (s == 1) ? (1.0f / (float)NPTS) : g_v[s - 1][ix];
            float nv = 0.5f * g_y[s][ix] / g_colsum[ix] + 0.5f * vprev;
            g_v[s][ix] = nv;
            vtj_h[tid - 128] = __float2half_rn(nv);
        }
    }

    float* yo = g_y[s + 1];
    int q2 = (lane & 3) * 2;

    // row-pass assignment (fixed per warp): row-half rh16, kc pair kcp
    int rh16 = (wid >> 2) * 16;              // 0 or 16
    int kcp  = (wid & 3) * 2;                // kc in {kcp, kcp+1}
    // transpose accumulator (columns wid*16..+15, fixed per warp)
    float dT[4] = {0.f, 0.f, 0.f, 0.f};

    #pragma unroll
    for (int q = 0; q < 4; q++) {
        // prefetch next quarter
        if (q < 3) {
            const __half* src = Kt + (size_t)(q + 1) * 32 * NPTS;
            uint32_t dst = qb[(q + 1) & 1];
            cp16(dst + ((uint32_t)(rl0 * LDA + c16 * 8) << 1),
                 &src[(size_t)rl0 * NPTS + c16 * 8]);
            cp16(dst + ((uint32_t)((rl0 + 16) * LDA + c16 * 8) << 1),
                 &src[(size_t)(rl0 + 16) * NPTS + c16 * 8]);
            cp_commit();
            cp_wait1();
        } else {
            cp_wait0();
        }
        __syncthreads();

        uint32_t qbc = qb[q & 1];

        // ---- row pass: rows q*32 + rh16 .. +15, k-chunks kcp, kcp+1 ----
        {
            float d[4] = {0.f, 0.f, 0.f, 0.f};
            uint32_t aRow = qbc +
                (((rh16 + (lane & 15)) * LDA + ((lane >> 4) << 3)) << 1);
            #pragma unroll
            for (int kk = 0; kk < 2; kk++) {
                int kc = kcp + kk;
                uint32_t A[4];
                ldm_x4(A, aRow + ((kc * 16) << 1));
                uint32_t b0 = *(const uint32_t*)&vtj_h[kc * 16 + q2];
                uint32_t b1 = *(const uint32_t*)&vtj_h[kc * 16 + q2 + 8];
                mma16816(d, A, b0, b1);
            }
            if ((lane & 3) == 0) {
                int row = q * 32 + rh16 + (lane >> 2);
                atomicAdd(&yo[base_ti + row],     d[0]);
                atomicAdd(&yo[base_ti + row + 8], d[2]);
            }
        }

        // ---- transpose pass: this quarter supplies k-chunks 2q, 2q+1 ----
        if (offdiag) {
            #pragma unroll
            for (int kk = 0; kk < 2; kk++) {
                int kglob = 2 * q + kk;
                uint32_t A[4];
                uint32_t aT = qbc +
                    (((kk * 16 + ((lane >> 4) << 3) + (lane & 7)) * LDA
                      + wid * 16 + (((lane >> 3) & 1) << 3)) << 1);
                ldm_x4_trans(A, aT);
                uint32_t b0 = *(const uint32_t*)&vti_h[kglob * 16 + q2];
                uint32_t b1 = *(const uint32_t*)&vti_h[kglob * 16 + q2 + 8];
                mma16816(dT, A, b0, b1);
            }
        }
        __syncthreads();
    }

    if (offdiag && (lane & 3) == 0) {
        int col = wid * 16 + (lane >> 2);
        atomicAdd(&yo[base_tj + col],     dT[0]);
        atomicAdd(&yo[base_tj + col + 8], dT[2]);
    }
}

// ---------------------------------------------------------------------------
// Kernel 4a: coalesced feats partials (computes v_8 inline from y_8).
// ---------------------------------------------------------------------------
__global__ void __launch_bounds__(256) feats_part_kernel() {
    __shared__ float vs[5][128];
    int chunk = blockIdx.x, g = blockIdx.y;
    int tid = threadIdx.x;

    if (tid < 128) {
        int ix = g * NPTS + chunk * 128 + tid;
        vs[0][tid] = 1.0f / (float)NPTS;
        vs[1][tid] = g_v[1][ix];
        vs[2][tid] = g_v[2][ix];
        vs[3][tid] = g_v[4][ix];
        vs[4][tid] = 0.5f * g_y[8][ix] / g_colsum[ix] + 0.5f * g_v[7][ix];
    }
    __syncthreads();

    int c = tid & 127, hf = tid >> 7;
    const float* X = g_Xb + ((size_t)g * NPTS + chunk * 128) * DIM;
    float acc[5] = {0.f, 0.f, 0.f, 0.f, 0.f};
    for (int n = hf; n < 128; n += 2) {
        float x = X[(size_t)n * DIM + c];
        #pragma unroll
        for (int tt = 0; tt < 5; tt++) acc[tt] += vs[tt][n] * x;
    }
    #pragma unroll
    for (int tt = 0; tt < 5; tt++)
        g_part[(((g * 16 + chunk) * 5 + tt) * 128 + c) * 2 + hf] = acc[tt];
}

// ---------------------------------------------------------------------------
// Kernel 4b: reduce partials over 16 chunks x 2 halves -> out
// ---------------------------------------------------------------------------
__global__ void __launch_bounds__(640) feats_reduce_kernel(float* __restrict__ out) {
    int g = blockIdx.x;
    int tid = threadIdx.x;
    int t = tid >> 7, c = tid & 127;
    float s = 0.f;
    #pragma unroll
    for (int ch = 0; ch < 16; ch++) {
        const float* p = &g_part[(((g * 16 + ch) * 5 + t) * 128 + c) * 2];
        s += p[0] + p[1];
    }
    out[g * 640 + t * 128 + c] = s;
}

// ---------------------------------------------------------------------------
extern "C" void kernel_launch(void* const* d_in, const int* in_sizes, int n_in,
                              void* d_out, int out_size) {
    const float* pc = (const float*)d_in[0];   // point_clouds [4,2048,128]
    const float* al = (const float*)d_in[1];   // alphas [4,128]
    const float* sg = (const float*)d_in[2];   // sigma scalar
    float* out = (float*)d_out;                // [4, 2560] fp32

    cudaFuncSetAttribute(gram_mma_kernel,
                         cudaFuncAttributeMaxDynamicSharedMemorySize, GRAM_SMEM);

    prep_kernel<<<NG * NPTS, DIM>>>(pc, al);

    dim3 ggrid(136, NG);
    gram_mma_kernel<<<ggrid, 256, GRAM_SMEM>>>(sg);

    dim3 sgrid(136, NG);
    for (int s = 0; s < 8; s++)
        step_mma_kernel<<<sgrid, 256>>>(s);

    dim3 fgrid(16, NG);
    feats_part_kernel<<<fgrid, 256>>>();
    feats_reduce_kernel<<<NG, 640>>>(out);
}

// round 13
// speedup vs baseline: 1.0583x; 1.0583x over previous
#include <cuda_runtime.h>
#include <cuda_fp16.h>
#include <cstdint>

#define NG   16
#define NPTS 2048
#define DIM  128
#define THRESH 1e-5f
#define LDA  136    // smem row stride in halves

// Scratch (static device globals; no allocations anywhere)
__device__ float  g_Xb[(size_t)NG*NPTS*DIM];          // fp32 Xb
__device__ __half g_Xh[(size_t)NG*NPTS*DIM];          // fp16 Xb (MMA)
__device__ float  g_diag[NG*NPTS];
__device__ float  g_colsum[NG*NPTS];
__device__ __half g_K[(size_t)NG*NPTS*NPTS];          // upper tiles only
__device__ float  g_v[9][NG*NPTS];
__device__ float  g_y[9][NG*NPTS];
__device__ float  g_part[NG*16*5*DIM*2];              // feats partials

// ---------------------------------------------------------------------------
// helpers (baseline PTX only: ldmatrix sm_75+, mma.sync + cp.async sm_80+)
// ---------------------------------------------------------------------------
__device__ __forceinline__ uint32_t smem_u32(const void* p) {
    return (uint32_t)__cvta_generic_to_shared(p);
}
__device__ __forceinline__ void cp16(uint32_t dst, const void* src) {
    asm volatile("cp.async.cg.shared.global [%0], [%1], 16;"
                 :: "r"(dst), "l"(src));
}
__device__ __forceinline__ void cp_commit() {
    asm volatile("cp.async.commit_group;" ::: "memory");
}
__device__ __forceinline__ void cp_wait0() {
    asm volatile("cp.async.wait_group 0;" ::: "memory");
}
__device__ __forceinline__ void ldm_x4(uint32_t* r, uint32_t addr) {
    asm volatile("ldmatrix.sync.aligned.m8n8.x4.shared.b16 {%0,%1,%2,%3}, [%4];"
                 : "=r"(r[0]), "=r"(r[1]), "=r"(r[2]), "=r"(r[3]) : "r"(addr));
}
__device__ __forceinline__ void ldm_x4_trans(uint32_t* r, uint32_t addr) {
    asm volatile("ldmatrix.sync.aligned.m8n8.x4.trans.shared.b16 {%0,%1,%2,%3}, [%4];"
                 : "=r"(r[0]), "=r"(r[1]), "=r"(r[2]), "=r"(r[3]) : "r"(addr));
}
__device__ __forceinline__ void mma16816(float* c, const uint32_t* a,
                                         uint32_t b0, uint32_t b1) {
    asm volatile(
        "mma.sync.aligned.m16n8k16.row.col.f32.f16.f16.f32 "
        "{%0,%1,%2,%3}, {%4,%5,%6,%7}, {%8,%9}, {%0,%1,%2,%3};"
        : "+f"(c[0]), "+f"(c[1]), "+f"(c[2]), "+f"(c[3])
        : "r"(a[0]), "r"(a[1]), "r"(a[2]), "r"(a[3]), "r"(b0), "r"(b1));
}

// ---------------------------------------------------------------------------
// Kernel 1: Xb = pc*alpha (fp32 + fp16), diag, zero colsum + y buffers
// ---------------------------------------------------------------------------
__global__ void prep_kernel(const float* __restrict__ pc,
                            const float* __restrict__ al) {
    int gid = blockIdx.x;
    int g = gid >> 11;
    int n = gid & 2047;
    int b = g >> 2, w = g & 3;
    int c = threadIdx.x;
    float x = pc[((size_t)(b << 11) + n) * DIM + c] * al[w * DIM + c];
    g_Xb[(size_t)gid * DIM + c] = x;
    g_Xh[(size_t)gid * DIM + c] = __float2half_rn(x);
    float s = x * x;
    #pragma unroll
    for (int o = 16; o; o >>= 1) s += __shfl_xor_sync(0xffffffffu, s, o);
    __shared__ float red[4];
    if ((c & 31) == 0) red[c >> 5] = s;
    __syncthreads();
    if (c == 0) {
        g_diag[gid]   = red[0] + red[1] + red[2] + red[3];
        g_colsum[gid] = 0.f;
    }
    if (c >= 1 && c <= 8) g_y[c][gid] = 0.f;
}

// ---------------------------------------------------------------------------
// Kernel 2: HMMA Gram, upper-triangular tile pairs only (136 per graph).
// exp epilogue, fused row/col sums -> colsum. Upper tiles stored only.
// ---------------------------------------------------------------------------
#define GRAM_SMEM (2 * 128 * LDA * 2)

__global__ void __launch_bounds__(256) gram_mma_kernel(const float* __restrict__ sigma) {
    extern __shared__ __half smem[];
    __shared__ float dj_s[128];
    __shared__ float rs_s[128];
    __shared__ float cs_s[128];

    int tid = threadIdx.x, wid = tid >> 5, lane = tid & 31;
    int g = blockIdx.y;

    int idx = blockIdx.x, ti = 0;
    while (idx >= 16 - ti) { idx -= 16 - ti; ti++; }
    int tj = ti + idx;

    int warp_m = wid & 1;
    int warp_n = wid >> 1;

    __half* sA = smem;
    __half* sB = smem + 128 * LDA;
    uint32_t sAu = smem_u32(sA), sBu = smem_u32(sB);

    const __half* XA = g_Xh + ((size_t)g * NPTS + ti * 128) * DIM;
    const __half* XB = g_Xh + ((size_t)g * NPTS + tj * 128) * DIM;
    #pragma unroll
    for (int l = 0; l < 8; l++) {
        int ch  = tid + l * 256;
        int row = ch >> 4;
        int c8  = (ch & 15) << 3;
        uint32_t off = (uint32_t)(row * LDA + c8) << 1;
        cp16(sAu + off, &XA[(size_t)row * DIM + c8]);
        cp16(sBu + off, &XB[(size_t)row * DIM + c8]);
    }
    cp_commit();
    if (tid < 128) {
        dj_s[tid] = g_diag[g * NPTS + tj * 128 + tid];
        rs_s[tid] = 0.f;
        cs_s[tid] = 0.f;
    }
    cp_wait0();
    __syncthreads();

    uint32_t aBase = sAu +
        (((warp_m * 64 + (lane & 15)) * LDA + ((lane >> 4) << 3)) << 1);
    uint32_t bBase = sBu +
        (((warp_n * 32 + (lane & 15)) * LDA + ((lane >> 4) << 3)) << 1);

    float acc[4][4][4];
    #pragma unroll
    for (int mi = 0; mi < 4; mi++)
        #pragma unroll
        for (int ni = 0; ni < 4; ni++)
            #pragma unroll
            for (int e = 0; e < 4; e++) acc[mi][ni][e] = 0.f;

    #pragma unroll
    for (int ks = 0; ks < 8; ks++) {
        uint32_t Af[4][4], Bf[2][4];
        #pragma unroll
        for (int mi = 0; mi < 4; mi++)
            ldm_x4(Af[mi], aBase + ((mi * 16 * LDA + ks * 16) << 1));
        #pragma unroll
        for (int nj = 0; nj < 2; nj++)
            ldm_x4(Bf[nj], bBase + ((nj * 16 * LDA + ks * 16) << 1));
        #pragma unroll
        for (int mi = 0; mi < 4; mi++)
            #pragma unroll
            for (int ni = 0; ni < 4; ni++)
                mma16816(acc[mi][ni], Af[mi],
                         Bf[ni >> 1][ni & 1], Bf[ni >> 1][2 + (ni & 1)]);
    }

    float inv_s = 1.0f / *sigma;
    int r = lane >> 2, q = lane & 3;
    uint32_t h_up[4][4], h_lo[4][4];
    float csA[4] = {0.f, 0.f, 0.f, 0.f};
    float csB[4] = {0.f, 0.f, 0.f, 0.f};

    #pragma unroll
    for (int mi = 0; mi < 4; mi++) {
        int lr0 = warp_m * 64 + mi * 16 + r;
        float di0 = g_diag[g * NPTS + ti * 128 + lr0];
        float di1 = g_diag[g * NPTS + ti * 128 + lr0 + 8];
        float rs0 = 0.f, rs1 = 0.f;
        #pragma unroll
        for (int ni = 0; ni < 4; ni++) {
            int lc = warp_n * 32 + ni * 8 + q * 2;
            float dj0 = dj_s[lc], dj1 = dj_s[lc + 1];
            float* a = acc[mi][ni];
            float k00 = __expf(-(di0 + dj0 - 2.0f * a[0]) * inv_s);
            float k01 = __expf(-(di0 + dj1 - 2.0f * a[1]) * inv_s);
            float k10 = __expf(-(di1 + dj0 - 2.0f * a[2]) * inv_s);
            float k11 = __expf(-(di1 + dj1 - 2.0f * a[3]) * inv_s);
            k00 = (k00 < THRESH) ? 0.f : k00;
            k01 = (k01 < THRESH) ? 0.f : k01;
            k10 = (k10 < THRESH) ? 0.f : k10;
            k11 = (k11 < THRESH) ? 0.f : k11;
            rs0 += k00 + k01;
            rs1 += k10 + k11;
            csA[ni] += k00 + k10;
            csB[ni] += k01 + k11;
            __half2 h0 = __floats2half2_rn(k00, k01);
            __half2 h1 = __floats2half2_rn(k10, k11);
            h_up[mi][ni] = *reinterpret_cast<uint32_t*>(&h0);
            h_lo[mi][ni] = *reinterpret_cast<uint32_t*>(&h1);
        }
        rs0 += __shfl_xor_sync(0xffffffffu, rs0, 1);
        rs0 += __shfl_xor_sync(0xffffffffu, rs0, 2);
        rs1 += __shfl_xor_sync(0xffffffffu, rs1, 1);
        rs1 += __shfl_xor_sync(0xffffffffu, rs1, 2);
        if (q == 0) {
            atomicAdd(&rs_s[lr0], rs0);
            atomicAdd(&rs_s[lr0 + 8], rs1);
        }
    }
    #pragma unroll
    for (int ni = 0; ni < 4; ni++) {
        float a = csA[ni], b = csB[ni];
        #pragma unroll
        for (int o = 4; o <= 16; o <<= 1) {
            a += __shfl_xor_sync(0xffffffffu, a, o);
            b += __shfl_xor_sync(0xffffffffu, b, o);
        }
        if (r == 0) {
            atomicAdd(&cs_s[warp_n * 32 + ni * 8 + 2 * q], a);
            atomicAdd(&cs_s[warp_n * 32 + ni * 8 + 2 * q + 1], b);
        }
    }

    __half* Kg = g_K + (size_t)g * NPTS * NPTS;
    #pragma unroll
    for (int mi = 0; mi < 4; mi++) {
        int lr0 = warp_m * 64 + mi * 16 + r;
        #pragma unroll
        for (int ni = 0; ni < 4; ni++) {
            int lc = warp_n * 32 + ni * 8 + q * 2;
            size_t c0 = (size_t)(ti * 128 + lr0) * NPTS + tj * 128 + lc;
            *(uint32_t*)&Kg[c0]                    = h_up[mi][ni];
            *(uint32_t*)&Kg[c0 + 8 * (size_t)NPTS] = h_lo[mi][ni];
        }
    }

    __syncthreads();
    if (tid < 128) {
        atomicAdd(&g_colsum[g * NPTS + ti * 128 + tid], rs_s[tid]);
        if (ti != tj)
            atomicAdd(&g_colsum[g * NPTS + tj * 128 + tid], cs_s[tid]);
    }
}

// ---------------------------------------------------------------------------
// Kernel 3 (x8): fused normalize + symmetric mat-vec on tensor pipe.
// HALF-TILE CTAs: each CTA handles 64 rows (h=0,1) of upper tile (ti,tj).
// Warp-specialized compute: warps 0-3 row pass (16 rows x 8 kc each),
// warps 4-7 transpose pass (32 cols each, k-chunks 4h..4h+3) concurrently.
//   y[ti rows] += T_half * v[tj]
//   y[tj cols] += T_half^T * v[ti rows]
// ---------------------------------------------------------------------------
__global__ void __launch_bounds__(256) step_mma_kernel(int s) {
    __shared__ __half tile[64 * LDA];       // 17408 B
    __shared__ __half vti_h[128];
    __shared__ __half vtj_h[128];

    int tid = threadIdx.x, wid = tid >> 5, lane = tid & 31;
    int g = blockIdx.y;
    int pair = blockIdx.x >> 1;
    int h    = blockIdx.x & 1;
    int idx = pair, ti = 0;
    while (idx >= 16 - ti) { idx -= 16 - ti; ti++; }
    int tj = ti + idx;
    bool offdiag = (ti != tj);
    int base_ti = g * NPTS + ti * 128;
    int base_tj = g * NPTS + tj * 128;

    // issue the half-tile stream first (no register deps -> deep MLP)
    const __half* Kt = g_K + ((size_t)g * NPTS + ti * 128 + h * 64) * NPTS + tj * 128;
    uint32_t ts = smem_u32(tile);
    int rl0 = tid >> 4;          // 0..15
    int c16 = tid & 15;
    #pragma unroll
    for (int l = 0; l < 4; l++) {
        int row = rl0 + l * 16;  // 0..63
        cp16(ts + ((uint32_t)(row * LDA + c16 * 8) << 1),
             &Kt[(size_t)row * NPTS + c16 * 8]);
    }
    cp_commit();

    // normalize phase overlaps the copies (redundant identical writes OK)
    if (s == 0) {
        __half h0 = __float2half_rn(1.0f / (float)NPTS);   // exact in fp16
        if (tid < 128) vti_h[tid] = h0;
        else           vtj_h[tid - 128] = h0;
    } else {
        if (tid < 128) {
            int ix = base_ti + tid;
            float vprev = (s == 1) ? (1.0f / (float)NPTS) : g_v[s - 1][ix];
            float nv = 0.5f * g_y[s][ix] / g_colsum[ix] + 0.5f * vprev;
            g_v[s][ix] = nv;
            vti_h[tid] = __float2half_rn(nv);
        } else {
            int ix = base_tj + (tid - 128);
            float vprev = (s == 1) ? (1.0f / (float)NPTS) : g_v[s - 1][ix];
            float nv = 0.5f * g_y[s][ix] / g_colsum[ix] + 0.5f * vprev;
            g_v[s][ix] = nv;
            vtj_h[tid - 128] = __float2half_rn(nv);
        }
    }

    cp_wait0();
    __syncthreads();

    float* yo = g_y[s + 1];
    int q2 = (lane & 3) * 2;

    if (wid < 4) {
        // ---- row pass: warp owns local rows wid*16..+15, all 8 k-chunks ----
        float d[4] = {0.f, 0.f, 0.f, 0.f};
        uint32_t aRow = ts +
            (((wid * 16 + (lane & 15)) * LDA + ((lane >> 4) << 3)) << 1);
        #pragma unroll
        for (int kc = 0; kc < 8; kc++) {
            uint32_t A[4];
            ldm_x4(A, aRow + ((kc * 16) << 1));
            uint32_t b0 = *(const uint32_t*)&vtj_h[kc * 16 + q2];
            uint32_t b1 = *(const uint32_t*)&vtj_h[kc * 16 + q2 + 8];
            mma16816(d, A, b0, b1);
        }
        if ((lane & 3) == 0) {
            int row = h * 64 + wid * 16 + (lane >> 2);
            atomicAdd(&yo[base_ti + row],     d[0]);
            atomicAdd(&yo[base_ti + row + 8], d[2]);
        }
    } else if (offdiag) {
        // ---- transpose pass: warp owns cols (wid-4)*32..+31; this half
        //      supplies k-chunks 4h..4h+3 (its 64 rows) ----
        int wt = wid - 4;
        float dT0[4] = {0.f, 0.f, 0.f, 0.f};
        float dT1[4] = {0.f, 0.f, 0.f, 0.f};
        #pragma unroll
        for (int kk = 0; kk < 4; kk++) {
            int kglob = h * 4 + kk;
            uint32_t b0 = *(const uint32_t*)&vti_h[kglob * 16 + q2];
            uint32_t b1 = *(const uint32_t*)&vti_h[kglob * 16 + q2 + 8];
            uint32_t rowpart = (uint32_t)(kk * 16 + ((lane >> 4) << 3) + (lane & 7));
            uint32_t colpart = (uint32_t)(wt * 32 + (((lane >> 3) & 1) << 3));
            uint32_t A[4];
            ldm_x4_trans(A, ts + ((rowpart * LDA + colpart) << 1));
            mma16816(dT0, A, b0, b1);
            ldm_x4_trans(A, ts + ((rowpart * LDA + colpart + 16) << 1));
            mma16816(dT1, A, b0, b1);
        }
        if ((lane & 3) == 0) {
            int col = wt * 32 + (lane >> 2);
            atomicAdd(&yo[base_tj + col],      dT0[0]);
            atomicAdd(&yo[base_tj + col + 8],  dT0[2]);
            atomicAdd(&yo[base_tj + col + 16], dT1[0]);
            atomicAdd(&yo[base_tj + col + 24], dT1[2]);
        }
    }
}

// ---------------------------------------------------------------------------
// Kernel 4a: coalesced feats partials (computes v_8 inline from y_8).
// ---------------------------------------------------------------------------
__global__ void __launch_bounds__(256) feats_part_kernel() {
    __shared__ float vs[5][128];
    int chunk = blockIdx.x, g = blockIdx.y;
    int tid = threadIdx.x;

    if (tid < 128) {
        int ix = g * NPTS + chunk * 128 + tid;
        vs[0][tid] = 1.0f / (float)NPTS;
        vs[1][tid] = g_v[1][ix];
        vs[2][tid] = g_v[2][ix];
        vs[3][tid] = g_v[4][ix];
        vs[4][tid] = 0.5f * g_y[8][ix] / g_colsum[ix] + 0.5f * g_v[7][ix];
    }
    __syncthreads();

    int c = tid & 127, hf = tid >> 7;
    const float* X = g_Xb + ((size_t)g * NPTS + chunk * 128) * DIM;
    float acc[5] = {0.f, 0.f, 0.f, 0.f, 0.f};
    for (int n = hf; n < 128; n += 2) {
        float x = X[(size_t)n * DIM + c];
        #pragma unroll
        for (int tt = 0; tt < 5; tt++) acc[tt] += vs[tt][n] * x;
    }
    #pragma unroll
    for (int tt = 0; tt < 5; tt++)
        g_part[(((g * 16 + chunk) * 5 + tt) * 128 + c) * 2 + hf] = acc[tt];
}

// ---------------------------------------------------------------------------
// Kernel 4b: reduce partials over 16 chunks x 2 halves -> out
// ---------------------------------------------------------------------------
__global__ void __launch_bounds__(640) feats_reduce_kernel(float* __restrict__ out) {
    int g = blockIdx.x;
    int tid = threadIdx.x;
    int t = tid >> 7, c = tid & 127;
    float s = 0.f;
    #pragma unroll
    for (int ch = 0; ch < 16; ch++) {
        const float* p = &g_part[(((g * 16 + ch) * 5 + t) * 128 + c) * 2];
        s += p[0] + p[1];
    }
    out[g * 640 + t * 128 + c] = s;
}

// ---------------------------------------------------------------------------
extern "C" void kernel_launch(void* const* d_in, const int* in_sizes, int n_in,
                              void* d_out, int out_size) {
    const float* pc = (const float*)d_in[0];   // point_clouds [4,2048,128]
    const float* al = (const float*)d_in[1];   // alphas [4,128]
    const float* sg = (const float*)d_in[2];   // sigma scalar
    float* out = (float*)d_out;                // [4, 2560] fp32

    cudaFuncSetAttribute(gram_mma_kernel,
                         cudaFuncAttributeMaxDynamicSharedMemorySize, GRAM_SMEM);

    prep_kernel<<<NG * NPTS, DIM>>>(pc, al);

    dim3 ggrid(136, NG);
    gram_mma_kernel<<<ggrid, 256, GRAM_SMEM>>>(sg);

    dim3 sgrid(272, NG);   // 2 half-tile CTAs per upper tile
    for (int s = 0; s < 8; s++)
        step_mma_kernel<<<sgrid, 256>>>(s);

    dim3 fgrid(16, NG);
    feats_part_kernel<<<fgrid, 256>>>();
    feats_reduce_kernel<<<NG, 640>>>(out);
}

// round 14
// speedup vs baseline: 26.9344x; 25.4517x over previous
#include <cuda_runtime.h>
#include <cstdint>

// out[g, t*128 + c] = alpha[w,c] * mean_n pc[b,n,c],  g = b*4 + w, all t.
// Derivation: P = 0.5*K/colsum + 0.5*I is column-stochastic (colsum taken
// over axis 1, the same axis mean-pooling reduces), so mean(P^t x) = mean(x)
// exactly for every t. The diffusion is a no-op under mean pooling.

__device__ float g_psum[4 * 16 * 128];   // (b, chunk, c) partial sums

// ---------------------------------------------------------------------------
// Kernel 1: partial sums over 128-point chunks. grid (16 chunks, 4 clouds),
// 256 threads (c = tid&127, half = tid>>7). Fully coalesced.
// ---------------------------------------------------------------------------
__global__ void __launch_bounds__(256) psum_kernel(const float* __restrict__ pc) {
    __shared__ float sh[128];
    int chunk = blockIdx.x, b = blockIdx.y;
    int c = threadIdx.x & 127, hf = threadIdx.x >> 7;

    const float* X = pc + ((size_t)b * 2048 + chunk * 128) * 128;
    float acc = 0.f;
    #pragma unroll 8
    for (int n = hf; n < 128; n += 2)
        acc += X[(size_t)n * 128 + c];

    if (hf == 0) sh[c] = acc;
    __syncthreads();
    if (hf == 1)
        g_psum[(b * 16 + chunk) * 128 + c] = sh[c] + acc;
}

// ---------------------------------------------------------------------------
// Kernel 2: write all outputs. 10240 = 16 graphs x 5 scales x 128 channels.
// ---------------------------------------------------------------------------
__global__ void __launch_bounds__(256) write_kernel(const float* __restrict__ al,
                                                    float* __restrict__ out) {
    int i = blockIdx.x * 256 + threadIdx.x;    // 0..10239
    int g = i / 640;
    int c = i & 127;                            // channel (t block irrelevant)
    int b = g >> 2, w = g & 3;

    float s = 0.f;
    #pragma unroll
    for (int ch = 0; ch < 16; ch++)
        s += g_psum[(b * 16 + ch) * 128 + c];

    out[i] = al[w * 128 + c] * (s * (1.0f / 2048.0f));
}

// ---------------------------------------------------------------------------
extern "C" void kernel_launch(void* const* d_in, const int* in_sizes, int n_in,
                              void* d_out, int out_size) {
    const float* pc = (const float*)d_in[0];   // point_clouds [4,2048,128]
    const float* al = (const float*)d_in[1];   // alphas [4,128]
    float* out = (float*)d_out;                // [4, 2560] fp32

    dim3 pgrid(16, 4);
    psum_kernel<<<pgrid, 256>>>(pc);
    write_kernel<<<40, 256>>>(al, out);
}